// round 1
// baseline (speedup 1.0000x reference)
#include <cuda_runtime.h>
#include <math.h>

// Problem dims (fixed by the dataset)
#define B_ 4096
#define D_ 1024
#define C_ 1000
#define P_ 2000

// ---------------- scratch (device globals; no allocations allowed) ----------
__device__ float g_rinv_f[B_];
__device__ float g_rinv_c[C_];
__device__ float g_rinv_p[P_];
__device__ float g_sims[(size_t)B_ * C_];    // 16.4 MB
__device__ float g_csims[(size_t)B_ * P_];   // 32.8 MB
__device__ float g_pos[B_];
__device__ float g_nce[B_];
__device__ float g_cross[B_];

// ---------------- block reduction helpers ----------------------------------
__device__ __forceinline__ float warpSum(float v) {
#pragma unroll
    for (int o = 16; o; o >>= 1) v += __shfl_down_sync(0xffffffffu, v, o);
    return v;
}
__device__ __forceinline__ float warpMax(float v) {
#pragma unroll
    for (int o = 16; o; o >>= 1) v = fmaxf(v, __shfl_down_sync(0xffffffffu, v, o));
    return v;
}
// Result valid on thread 0 only. Safe to call repeatedly (sync at entry).
__device__ __forceinline__ float blockReduceSum(float v) {
    __shared__ float sh[32];
    __syncthreads();
    int lane = threadIdx.x & 31, wid = threadIdx.x >> 5;
    v = warpSum(v);
    if (lane == 0) sh[wid] = v;
    __syncthreads();
    int nw = (blockDim.x + 31) >> 5;
    v = (threadIdx.x < nw) ? sh[threadIdx.x] : 0.f;
    if (wid == 0) v = warpSum(v);
    return v;
}
__device__ __forceinline__ float blockReduceMax(float v) {
    __shared__ float sh[32];
    __syncthreads();
    int lane = threadIdx.x & 31, wid = threadIdx.x >> 5;
    v = warpMax(v);
    if (lane == 0) sh[wid] = v;
    __syncthreads();
    int nw = (blockDim.x + 31) >> 5;
    v = (threadIdx.x < nw) ? sh[threadIdx.x] : -1e30f;
    if (wid == 0) v = warpMax(v);
    return v;
}

// ---------------- row inverse-norm ------------------------------------------
// which: 0 -> g_rinv_f, 1 -> g_rinv_c, 2 -> g_rinv_p
__global__ void rownorm_kernel(const float* __restrict__ X, int which) {
    float* rinv = (which == 0) ? g_rinv_f : (which == 1) ? g_rinv_c : g_rinv_p;
    int r = blockIdx.x;
    const float* x = X + (size_t)r * D_;
    float s = 0.f;
    for (int j = threadIdx.x; j < D_; j += blockDim.x) {
        float v = x[j];
        s += v * v;
    }
    s = blockReduceSum(s);
    if (threadIdx.x == 0) rinv[r] = 1.0f / fmaxf(sqrtf(s), 1e-12f);
}

// ---------------- SGEMM: C[M,N] = scaleA[m]*scaleB[n] * (A[M,K] · B[N,K]^T) --
// 128x128 tile, BK=8, 256 threads, 8x8 per-thread microtile.
#define BM 128
#define BN 128
#define BK 8
#define TM 8
#define TN 8

// sel: 0 -> (rinvA=g_rinv_f, rinvB=g_rinv_c, C=g_sims,  N=C_)
//      1 -> (rinvA=g_rinv_f, rinvB=g_rinv_p, C=g_csims, N=P_)
__global__ __launch_bounds__(256, 1)
void sgemm_nt_scaled(const float* __restrict__ A, const float* __restrict__ Bm, int sel) {
    const int N = (sel == 0) ? C_ : P_;
    const float* __restrict__ rinvA = g_rinv_f;
    const float* __restrict__ rinvB = (sel == 0) ? g_rinv_c : g_rinv_p;
    float* __restrict__ Cout = (sel == 0) ? g_sims : g_csims;
    const int K = D_;

    __shared__ float As[BK][BM];
    __shared__ float Bs[BK][BN];

    const int tid = threadIdx.x;
    const int tx = tid & 15;     // 0..15 (N direction)
    const int ty = tid >> 4;     // 0..15 (M direction)
    const int rowA0 = blockIdx.y * BM;
    const int colB0 = blockIdx.x * BN;

    const int lrow = tid >> 1;          // 0..127
    const int lcol = (tid & 1) << 2;    // 0 or 4

    const float* Aptr = A + (size_t)(rowA0 + lrow) * K + lcol;
    const bool bvalid = (colB0 + lrow) < N;
    const float* Bptr = Bm + (size_t)(colB0 + lrow) * K + lcol;

    float acc[TM][TN];
#pragma unroll
    for (int i = 0; i < TM; i++)
#pragma unroll
        for (int j = 0; j < TN; j++) acc[i][j] = 0.f;

    for (int k0 = 0; k0 < K; k0 += BK) {
        float4 av = *reinterpret_cast<const float4*>(Aptr + k0);
        float4 bv = bvalid ? *reinterpret_cast<const float4*>(Bptr + k0)
                           : make_float4(0.f, 0.f, 0.f, 0.f);
        __syncthreads();
        As[lcol + 0][lrow] = av.x;
        As[lcol + 1][lrow] = av.y;
        As[lcol + 2][lrow] = av.z;
        As[lcol + 3][lrow] = av.w;
        Bs[lcol + 0][lrow] = bv.x;
        Bs[lcol + 1][lrow] = bv.y;
        Bs[lcol + 2][lrow] = bv.z;
        Bs[lcol + 3][lrow] = bv.w;
        __syncthreads();

#pragma unroll
        for (int k = 0; k < BK; k++) {
            float4 a0 = *reinterpret_cast<const float4*>(&As[k][ty * TM]);
            float4 a1 = *reinterpret_cast<const float4*>(&As[k][ty * TM + 4]);
            float4 b0 = *reinterpret_cast<const float4*>(&Bs[k][tx * TN]);
            float4 b1 = *reinterpret_cast<const float4*>(&Bs[k][tx * TN + 4]);
            float ar[TM] = {a0.x, a0.y, a0.z, a0.w, a1.x, a1.y, a1.z, a1.w};
            float br[TN] = {b0.x, b0.y, b0.z, b0.w, b1.x, b1.y, b1.z, b1.w};
#pragma unroll
            for (int i = 0; i < TM; i++)
#pragma unroll
                for (int j = 0; j < TN; j++) acc[i][j] += ar[i] * br[j];
        }
    }

    // epilogue: scale by rinvA[row]*rinvB[col], guarded stores (M divides 128)
    float ra[TM], rb[TN];
#pragma unroll
    for (int i = 0; i < TM; i++) ra[i] = rinvA[rowA0 + ty * TM + i];
#pragma unroll
    for (int j = 0; j < TN; j++) {
        int col = colB0 + tx * TN + j;
        rb[j] = (col < N) ? rinvB[col] : 0.f;
    }
#pragma unroll
    for (int i = 0; i < TM; i++) {
        int row = rowA0 + ty * TM + i;
#pragma unroll
        for (int j = 0; j < TN; j++) {
            int col = colB0 + tx * TN + j;
            if (col < N) Cout[(size_t)row * N + col] = acc[i][j] * ra[i] * rb[j];
        }
    }
}

// ---------------- intra-domain InfoNCE + positive alignment -----------------
__global__ __launch_bounds__(256)
void reduce_intra_kernel(const int* __restrict__ labels) {
    const int i = blockIdx.x;
    const float* row = g_sims + (size_t)i * C_;
    __shared__ float srow[C_];
    for (int j = threadIdx.x; j < C_; j += blockDim.x) srow[j] = row[j];
    __syncthreads();

    float s = 0.f, s2 = 0.f, mx = -1e30f;
    for (int j = threadIdx.x; j < C_; j += blockDim.x) {
        float v = srow[j];
        s += v;
        s2 += v * v;
        mx = fmaxf(mx, v);
    }
    s = blockReduceSum(s);
    s2 = blockReduceSum(s2);
    mx = blockReduceMax(mx);

    __shared__ float sh_t, sh_m;
    if (threadIdx.x == 0) {
        float var = (s2 - s * s / (float)C_) / (float)(C_ - 1);
        float sd = sqrtf(fmaxf(var, 0.f));
        float t = fminf(fmaxf(0.07f * (1.f + sd), 0.01f), 0.5f);
        sh_t = t;
        sh_m = mx / t;
    }
    __syncthreads();
    const float t = sh_t, mlog = sh_m;

    float se = 0.f;
    for (int j = threadIdx.x; j < C_; j += blockDim.x)
        se += expf(srow[j] / t - mlog);
    se = blockReduceSum(se);

    if (threadIdx.x == 0) {
        int lab = labels[i];
        float pv = srow[lab];                  // = pos cosine
        g_nce[i] = mlog + logf(se) - pv / t;   // logsumexp - pos_logit
        g_pos[i] = 1.f - pv;
    }
}

// ---------------- cross-domain masked logsumexp ------------------------------
__global__ __launch_bounds__(256)
void reduce_cross_kernel(const int* __restrict__ labels, const int* __restrict__ ppl) {
    const int i = blockIdx.x;
    const int lab = labels[i];
    const float* row = g_csims + (size_t)i * P_;
    __shared__ float srow[P_];
    __shared__ unsigned char smask[P_];
    for (int j = threadIdx.x; j < P_; j += blockDim.x) {
        srow[j] = row[j];
        smask[j] = (ppl[j] != lab) ? 1 : 0;
    }
    __syncthreads();

    float s = 0.f, s2 = 0.f, mx = -1e30f, cnt = 0.f;
    for (int j = threadIdx.x; j < P_; j += blockDim.x) {
        if (smask[j]) {
            float v = srow[j];
            s += v;
            s2 += v * v;
            mx = fmaxf(mx, v);
            cnt += 1.f;
        }
    }
    s = blockReduceSum(s);
    s2 = blockReduceSum(s2);
    cnt = blockReduceSum(cnt);
    mx = blockReduceMax(mx);

    __shared__ float sh_t, sh_m;
    if (threadIdx.x == 0) {
        float n = cnt;
        float var = (s2 - s * s / n) / (n - 1.f);
        float sd = sqrtf(fmaxf(var, 0.f));
        float t = 2.f * fminf(fmaxf(0.07f * (1.f + sd), 0.01f), 0.5f);
        sh_t = t;
        sh_m = mx / t;
    }
    __syncthreads();
    const float t = sh_t, mlog = sh_m;

    float se = 0.f;
    for (int j = threadIdx.x; j < P_; j += blockDim.x)
        if (smask[j]) se += expf(srow[j] / t - mlog);
    se = blockReduceSum(se);

    if (threadIdx.x == 0) g_cross[i] = mlog + logf(se);
}

// ---------------- deterministic final combine --------------------------------
__global__ __launch_bounds__(1024)
void finalize_kernel(float* __restrict__ out) {
    float sp = 0.f, sn = 0.f, sc = 0.f;
    for (int i = threadIdx.x; i < B_; i += blockDim.x) {
        sp += g_pos[i];
        sn += g_nce[i];
        sc += g_cross[i];
    }
    sp = blockReduceSum(sp);
    sn = blockReduceSum(sn);
    sc = blockReduceSum(sc);
    if (threadIdx.x == 0) {
        const float invB = 1.0f / (float)B_;
        const float w = 0.1f + 0.9f * (1.0f / 1000.0f);   // step 1 / warmup 1000
        const float beta = 0.5f * w;                       // BETA * w
        out[0] = sp * invB + beta * (sn * invB + 0.3f * sc * invB);
    }
}

// ---------------- launch ------------------------------------------------------
extern "C" void kernel_launch(void* const* d_in, const int* in_sizes, int n_in,
                              void* d_out, int out_size) {
    const float* features  = (const float*)d_in[0];
    const float* cur_proto = (const float*)d_in[1];
    const float* prev_proto= (const float*)d_in[2];
    const int*   labels    = (const int*)d_in[3];
    const int*   ppl       = (const int*)d_in[4];
    float* out = (float*)d_out;

    // 1) row inverse norms
    rownorm_kernel<<<B_, 256>>>(features, 0);
    rownorm_kernel<<<C_, 256>>>(cur_proto, 1);
    rownorm_kernel<<<P_, 256>>>(prev_proto, 2);

    // 2) scaled GEMMs (normalization folded into epilogue)
    {
        dim3 grid1((C_ + BN - 1) / BN, B_ / BM);
        sgemm_nt_scaled<<<grid1, 256>>>(features, cur_proto, 0);
        dim3 grid2((P_ + BN - 1) / BN, B_ / BM);
        sgemm_nt_scaled<<<grid2, 256>>>(features, prev_proto, 1);
    }

    // 3) per-sample reductions
    reduce_intra_kernel<<<B_, 256>>>(labels);
    reduce_cross_kernel<<<B_, 256>>>(labels, ppl);

    // 4) combine
    finalize_kernel<<<1, 1024>>>(out);
}